// round 17
// baseline (speedup 1.0000x reference)
#include <cuda_runtime.h>
#include <cuda_fp16.h>
#include <cstdint>

#define TC      16
#define HID     128
#define PCH     48
#define THREADS 256
#define NTILE2  4096                // double-row tiles: 32 batches * 128

#define GS_STR  264                 // halfs per Gsh row; halo col 3, interior 4..259, halo 260
#define AT_STR  520                 // halfs per AsT row (260 words; 260 mod 32 = 4 -> conflict-free)
#define W1_STR  56
#define W2_STR  136

// smem: Gsh half[16*5*264] | AsT half[48*520] | Wh1 half[128*56] | Wh2 half[16*136]
#define OFF_GS   0
#define OFF_AST  (16*5*GS_STR*2)                  // 42240
#define OFF_WH1  (OFF_AST + PCH*AT_STR*2)         // 92160
#define OFF_WH2  (OFF_WH1 + HID*W1_STR*2)         // 106496
#define SMEM_BYTES (OFF_WH2 + TC*W2_STR*2)        // 110848

// Pre-converted, pre-padded weights (k-permuted w1: k = 16*filter + channel).
// Sobel rows (f=1,2) pre-scaled by 0.125.
__device__ __align__(16) half  g_wh1p[HID * W1_STR];
__device__ __align__(16) half  g_wh2p[TC * W2_STR];
__device__ __align__(16) half2 g_b1h2[HID / 2];

__global__ void convert_weights_kernel(const float* __restrict__ w1,
                                       const float* __restrict__ b1,
                                       const float* __restrict__ w2)
{
    int t = threadIdx.x;
    for (int i = t; i < HID * W1_STR; i += THREADS) g_wh1p[i] = __float2half(0.f);
    for (int i = t; i < TC * W2_STR; i += THREADS) g_wh2p[i] = __float2half(0.f);
    __syncthreads();
    for (int i = t; i < HID * PCH; i += THREADS) {
        int o = i / PCH, p = i % PCH;
        int c = p / 3, f = p % 3;                  // src col p = 3c+f
        float scale = (f == 0) ? 1.f : 0.125f;
        g_wh1p[o * W1_STR + f * 16 + c] = __float2half(w1[i] * scale);
    }
    for (int i = t; i < TC * HID; i += THREADS)
        g_wh2p[(i / HID) * W2_STR + (i % HID)] = __float2half(w2[i]);
    if (t < HID / 2)
        g_b1h2[t] = __floats2half2_rn(b1[2 * t], b1[2 * t + 1]);
}

__device__ __forceinline__ void mma_f16acc(unsigned* d,
    unsigned a0, unsigned a1, unsigned a2, unsigned a3,
    unsigned b0, unsigned b1)
{
    asm volatile(
        "mma.sync.aligned.m16n8k16.row.col.f16.f16.f16.f16 "
        "{%0,%1}, {%2,%3,%4,%5}, {%6,%7}, {%0,%1};\n"
        : "+r"(d[0]), "+r"(d[1])
        : "r"(a0), "r"(a1), "r"(a2), "r"(a3), "r"(b0), "r"(b1));
}

__device__ __forceinline__ void mma_f32acc(float* d,
    unsigned a0, unsigned a1, unsigned a2, unsigned a3,
    unsigned b0, unsigned b1)
{
    asm volatile(
        "mma.sync.aligned.m16n8k16.row.col.f32.f16.f16.f32 "
        "{%0,%1,%2,%3}, {%4,%5,%6,%7}, {%8,%9}, {%0,%1,%2,%3};\n"
        : "+f"(d[0]), "+f"(d[1]), "+f"(d[2]), "+f"(d[3])
        : "r"(a0), "r"(a1), "r"(a2), "r"(a3), "r"(b0), "r"(b1));
}

__device__ __forceinline__ void ldm_x4(unsigned& r0, unsigned& r1,
                                       unsigned& r2, unsigned& r3, uint32_t addr)
{
    asm volatile(
        "ldmatrix.sync.aligned.m8n8.x4.shared.b16 {%0,%1,%2,%3}, [%4];\n"
        : "=r"(r0), "=r"(r1), "=r"(r2), "=r"(r3) : "r"(addr));
}

__device__ __forceinline__ void ldm_x4_trans(unsigned& r0, unsigned& r1,
                                             unsigned& r2, unsigned& r3, uint32_t addr)
{
    asm volatile(
        "ldmatrix.sync.aligned.m8n8.x4.trans.shared.b16 {%0,%1,%2,%3}, [%4];\n"
        : "=r"(r0), "=r"(r1), "=r"(r2), "=r"(r3) : "r"(addr));
}

__device__ __forceinline__ unsigned hfma2_relu_bias(unsigned a, unsigned bias)
{
    unsigned d;
    const unsigned one2 = 0x3C003C00u;
    asm("fma.rn.relu.f16x2 %0, %1, %2, %3;\n" : "=r"(d) : "r"(a), "r"(one2), "r"(bias));
    return d;
}

__device__ __forceinline__ uint2 pack4h(float a, float b, float c, float d)
{
    half2 p0 = __floats2half2_rn(a, b);
    half2 p1 = __floats2half2_rn(c, d);
    return make_uint2(*(unsigned*)&p0, *(unsigned*)&p1);
}

__global__ __launch_bounds__(THREADS, 2)
void nca_step_kernel(const float* __restrict__ grid,
                     const float* __restrict__ noise,
                     const float* __restrict__ b2,
                     float* __restrict__ out,
                     int ncta)
{
    extern __shared__ __align__(128) char smem_raw[];
    half* Gsh = (half*)(smem_raw + OFF_GS);        // [16][5 slots][264] fp16, slot = row mod 5
    half* AsT = (half*)(smem_raw + OFF_AST);       // [48][520] k-major (cols = 512 pixels)
    half* Wh1 = (half*)(smem_raw + OFF_WH1);       // [128][56]
    half* Wh2 = (half*)(smem_raw + OFF_WH2);       // [16][136]

    const int tid = threadIdx.x;
    const int cta = blockIdx.x;

    const int base  = NTILE2 / ncta;
    const int rem   = NTILE2 % ncta;
    const int start = cta * base + (cta < rem ? cta : rem);
    const int cnt   = base + (cta < rem ? 1 : 0);

    // ---- stage weights once per CTA ----
    {
        const uint4* s1 = (const uint4*)g_wh1p;
        uint4*       d1 = (uint4*)Wh1;
        for (int i = tid; i < (HID*W1_STR)/8; i += THREADS) d1[i] = s1[i];
        const uint4* s2 = (const uint4*)g_wh2p;
        uint4*       d2 = (uint4*)Wh2;
        for (int i = tid; i < (TC*W2_STR)/8; i += THREADS) d2[i] = s2[i];
    }
    // static side halo cols (3 and 260) of all 5 slots x 16 ch -> zero once
    if (tid < 160) {
        int rowid = tid >> 1;                      // c*5 + slot, 0..79
        int side  = tid & 1;
        Gsh[rowid * GS_STR + (side ? 260 : 3)] = __float2half(0.f);
    }

    // ---- per-thread constants ----
    const int lane = tid & 31;
    const int wid  = tid >> 5;
    const int g    = lane >> 2;
    const int tg   = lane & 3;
    const int wq   = wid & 3;                      // pixel quarter within its row
    const int wr   = wid >> 2;                     // which of the 2 image rows
    const int m0c  = (wq << 6) + (wr << 8);        // AsT col base of this warp's 64 px
    const int m0r  = wq << 6;                      // pixel base within the image row

    const uint32_t ast_sm = (uint32_t)__cvta_generic_to_shared(AsT);
    const uint32_t a_row  = (lane & 7) + ((lane >> 4) << 3);
    const uint32_t a_base = ast_sm
        + (uint32_t)((a_row * AT_STR + m0c + (lane & 8)) * 2);
    const uint32_t brow = (lane & 7) + ((lane >> 4) << 3);
    const uint32_t bkof = (lane & 8);
    const uint32_t b1_base = (uint32_t)__cvta_generic_to_shared(Wh1) + (brow * W1_STR + bkof) * 2;
    const uint32_t b2_base = (uint32_t)__cvta_generic_to_shared(Wh2) + (brow * W2_STR + bkof) * 2;

    float bb_[2][2];
    #pragma unroll
    for (int nt = 0; nt < 2; nt++)
        #pragma unroll
        for (int rr = 0; rr < 2; rr++)
            bb_[nt][rr] = b2[(nt << 3) + 2*tg + rr];

    __syncthreads();

    for (int i = 0; i < cnt; i++) {
        const int tile = start + i;
        const int b    = tile >> 7;
        const int hp   = tile & 127;
        const int h    = hp << 1;                  // rows h, h+1 this tile

        // slots q[k] = (h-1+k) mod 5, k=0..3  (rows h-1 .. h+2)
        int q0 = (h + 4) % 5;
        int q1 = q0 + 1; if (q1 == 5) q1 = 0;
        int q2 = q1 + 1; if (q2 == 5) q2 = 0;
        int q3 = q2 + 1; if (q3 == 5) q3 = 0;

        if (i == 0 || hp == 0) {
            if (i > 0) __syncthreads();            // full restage touches slots prev epi reads
            // full restage rows h-1..h+2 (OOB -> 0)
            #pragma unroll
            for (int j = 0; j < 16; j++) {
                int idx   = j * THREADS + tid;     // 0..4095
                int rw    = idx >> 10;             // 0..3 -> row h-1+rw
                int c     = (idx >> 6) & 15;
                int colq  = idx & 63;
                int r_img = h - 1 + rw;
                int slot  = (rw == 0) ? q0 : (rw == 1) ? q1 : (rw == 2) ? q2 : q3;
                float4 v  = make_float4(0.f, 0.f, 0.f, 0.f);
                if ((unsigned)r_img < 256u)
                    v = *(const float4*)&grid[((((b*TC + c) << 8) + r_img) << 8) + (colq << 2)];
                *(uint2*)&Gsh[(c*5 + slot)*GS_STR + 4 + (colq << 2)] =
                    pack4h(v.x, v.y, v.z, v.w);
            }
        } else {
            // steady: rows h+1, h+2 are new (h-1, h already resident)
            #pragma unroll
            for (int j = 0; j < 8; j++) {
                int idx   = j * THREADS + tid;     // 0..2047
                int rw    = idx >> 10;             // 0..1 -> row h+1+rw
                int c     = (idx >> 6) & 15;
                int colq  = idx & 63;
                int r_img = h + 1 + rw;
                int slot  = rw ? q3 : q2;
                float4 v  = make_float4(0.f, 0.f, 0.f, 0.f);
                if (r_img < 256)
                    v = *(const float4*)&grid[((((b*TC + c) << 8) + r_img) << 8) + (colq << 2)];
                *(uint2*)&Gsh[(c*5 + slot)*GS_STR + 4 + (colq << 2)] =
                    pack4h(v.x, v.y, v.z, v.w);
            }
        }

        // ---- hoisted noise masks for this warp's image row ----
        const float* nrow = noise + (((b << 8) + h + wr) << 8);
        float mk_[4][2];
        #pragma unroll
        for (int s = 0; s < 4; s++) {
            mk_[s][0] = (nrow[m0r + 16*s + g]     < 0.5f) ? 1.f : 0.f;
            mk_[s][1] = (nrow[m0r + 16*s + g + 8] < 0.5f) ? 1.f : 0.f;
        }

        __syncthreads();                           // staged rows visible

        // ---- perception: 8 its x (1 ch, 4 px); AsT col = global px (0..511) ----
        #pragma unroll
        for (int it = 0; it < 8; it++) {
            int idx   = it * THREADS + tid;
            int c     = idx >> 7;                  // channel 0..15 (= it*2 + tid>>7)
            int grp   = tid & 127;                 // px quad 0..127 (warp-contiguous)
            int r_out = grp >> 6;                  // image row offset 0/1 (warp-uniform)
            int prw   = (grp & 63) << 2;           // pixel within row
            int col   = grp << 2;                  // AsT column

            // slots for stencil rows (h-1+r_out+r), r=0..2
            int sl0 = r_out ? q1 : q0;
            int sl1 = r_out ? q2 : q1;
            int sl2 = r_out ? q3 : q2;

            float t_[6], mr_[6], bt[6];
            #pragma unroll
            for (int r = 0; r < 3; r++) {
                const int slot = (r == 0) ? sl0 : (r == 1) ? sl1 : sl2;
                const int R = c * 5 + slot;
                uint2 hv = *(const uint2*)&Gsh[R * GS_STR + 4 + prw];
                float2 fa = __half22float2(*(half2*)&hv.x);
                float2 fb = __half22float2(*(half2*)&hv.y);
                float lft = __shfl_up_sync(0xffffffffu, fb.y, 1);
                float rgt = __shfl_down_sync(0xffffffffu, fa.x, 1);
                if (lane == 0)  lft = __half2float(Gsh[R * GS_STR + 3 + prw]);
                if (lane == 31) rgt = __half2float(Gsh[R * GS_STR + 8 + prw]);
                float* a = (r == 0) ? t_ : (r == 1) ? mr_ : bt;
                a[0] = lft; a[1] = fa.x; a[2] = fa.y; a[3] = fb.x; a[4] = fb.y; a[5] = rgt;
            }

            float idv[4], sxv[4], syv[4];
            #pragma unroll
            for (int j = 0; j < 4; j++) {
                // sobel_x = [[1,0,1],[2,0,-2],[1,0,-1]]/8 ; sobel_y std (/8 in w1)
                float u  = t_[j] + t_[j+2];
                idv[j] = mr_[j+1];
                sxv[j] = u + 2.f*(mr_[j] - mr_[j+2]) + bt[j] - bt[j+2];
                syv[j] = u + 2.f*t_[j+1] - bt[j] - 2.f*bt[j+1] - bt[j+2];
            }

            *(uint2*)&AsT[c        * AT_STR + col] = pack4h(idv[0], idv[1], idv[2], idv[3]);
            *(uint2*)&AsT[(16 + c) * AT_STR + col] = pack4h(sxv[0], sxv[1], sxv[2], sxv[3]);
            *(uint2*)&AsT[(32 + c) * AT_STR + col] = pack4h(syv[0], syv[1], syv[2], syv[3]);
        }
        __syncthreads();                           // AsT complete

        // ---- load & CACHE all A fragments: 4 sub-tiles x 3 kt ----
        unsigned aF[4][3][4];
        #pragma unroll
        for (int sb = 0; sb < 4; sb++)
            #pragma unroll
            for (int kt = 0; kt < 3; kt++)
                ldm_x4_trans(aF[sb][kt][0], aF[sb][kt][1], aF[sb][kt][2], aF[sb][kt][3],
                             a_base + (uint32_t)((kt * 16 * AT_STR + sb * 16) * 2));

        // ---- GEMM over 8 N-splits (2 hidden n-tiles each) ----
        float acc2[4][2][4];
        #pragma unroll
        for (int sb = 0; sb < 4; sb++)
            #pragma unroll
            for (int nt = 0; nt < 2; nt++) {
                acc2[sb][nt][0] = 0.f; acc2[sb][nt][1] = 0.f;
                acc2[sb][nt][2] = 0.f; acc2[sb][nt][3] = 0.f;
            }

        #pragma unroll
        for (int e = 0; e < 8; e++) {
            unsigned acc[4][2][2];
            #pragma unroll
            for (int sb = 0; sb < 4; sb++) {
                acc[sb][0][0] = 0u; acc[sb][0][1] = 0u;
                acc[sb][1][0] = 0u; acc[sb][1][1] = 0u;
            }
            #pragma unroll
            for (int kt = 0; kt < 3; kt++) {
                unsigned b0, b1r, b2r, b3;
                ldm_x4(b0, b1r, b2r, b3,
                       b1_base + (uint32_t)(e * 16 * W1_STR * 2) + kt * 32);
                #pragma unroll
                for (int sb = 0; sb < 4; sb++) {
                    mma_f16acc(acc[sb][0], aF[sb][kt][0], aF[sb][kt][1],
                               aF[sb][kt][2], aF[sb][kt][3], b0,  b1r);
                    mma_f16acc(acc[sb][1], aF[sb][kt][0], aF[sb][kt][1],
                               aF[sb][kt][2], aF[sb][kt][3], b2r, b3);
                }
            }
            // bias + relu: global nt = 2e+ntp -> half2 idx = tg + 8e + 4*ntp
            {
                const half2* B1p = g_b1h2 + (e << 3) + tg;
                unsigned bb0 = *(unsigned*)&B1p[0];
                unsigned bb1 = *(unsigned*)&B1p[4];
                #pragma unroll
                for (int sb = 0; sb < 4; sb++) {
                    acc[sb][0][0] = hfma2_relu_bias(acc[sb][0][0], bb0);
                    acc[sb][0][1] = hfma2_relu_bias(acc[sb][0][1], bb0);
                    acc[sb][1][0] = hfma2_relu_bias(acc[sb][1][0], bb1);
                    acc[sb][1][1] = hfma2_relu_bias(acc[sb][1][1], bb1);
                }
            }
            // GEMM2 partial: K chunk [16e, 16e+16) -> kt2 = e
            {
                unsigned b0, b1r, b2r, b3;
                ldm_x4(b0, b1r, b2r, b3, b2_base + e * 32);
                #pragma unroll
                for (int sb = 0; sb < 4; sb++) {
                    mma_f32acc(acc2[sb][0], acc[sb][0][0], acc[sb][0][1],
                               acc[sb][1][0], acc[sb][1][1], b0,  b1r);
                    mma_f32acc(acc2[sb][1], acc[sb][0][0], acc[sb][0][1],
                               acc[sb][1][0], acc[sb][1][1], b2r, b3);
                }
            }
        }

        // ---- epilogue: 64 px x 16 ch per warp; residual slot = q1+wr ----
        const int sres = wr ? q2 : q1;             // slot of row h+wr
        const int out_base = ((b*TC) << 16) + ((h + wr) << 8);

        #pragma unroll
        for (int sb = 0; sb < 4; sb++) {
            const int pix0 = m0r + 16*sb + g;
            const int pix1 = pix0 + 8;
            const float mk0 = mk_[sb][0];
            const float mk1 = mk_[sb][1];
            #pragma unroll
            for (int nt = 0; nt < 2; nt++) {
                #pragma unroll
                for (int rr = 0; rr < 2; rr++) {
                    int   c   = (nt << 3) + 2*tg + rr;
                    float gc0 = __half2float(Gsh[(c*5 + sres)*GS_STR + pix0 + 4]);
                    float gc1 = __half2float(Gsh[(c*5 + sres)*GS_STR + pix1 + 4]);
                    float u0  = (acc2[sb][nt][rr]     + bb_[nt][rr]) * mk0;
                    float u1  = (acc2[sb][nt][2 + rr] + bb_[nt][rr]) * mk1;
                    out[out_base + (c << 16) + pix0] = fminf(fmaxf(gc0 + u0, -2.f), 2.f);
                    out[out_base + (c << 16) + pix1] = fminf(fmaxf(gc1 + u1, -2.f), 2.f);
                }
            }
        }
        // no trailing barrier: next steady staging writes slots q3+1, q3+2 (mod 5),
        // disjoint from this epilogue's reads (q1, q2); full restage case has its
        // own leading barrier.
    }
}

extern "C" void kernel_launch(void* const* d_in, const int* in_sizes, int n_in,
                              void* d_out, int out_size)
{
    const float* grid  = (const float*)d_in[0];
    const float* noise = (const float*)d_in[1];
    const float* w1    = (const float*)d_in[2];
    const float* b1    = (const float*)d_in[3];
    const float* w2    = (const float*)d_in[4];
    const float* b2    = (const float*)d_in[5];
    float* out = (float*)d_out;

    static bool attr_set = false;
    if (!attr_set) {
        cudaFuncSetAttribute(nca_step_kernel,
                             cudaFuncAttributeMaxDynamicSharedMemorySize, SMEM_BYTES);
        attr_set = true;
    }

    int nsm = 148;
    cudaDeviceGetAttribute(&nsm, cudaDevAttrMultiProcessorCount, 0);
    int ncta = nsm * 2;
    if (ncta > NTILE2) ncta = NTILE2;

    convert_weights_kernel<<<1, THREADS>>>(w1, b1, w2);
    nca_step_kernel<<<ncta, THREADS, SMEM_BYTES>>>(grid, noise, b2, out, ncta);
}